// round 1
// baseline (speedup 1.0000x reference)
#include <cuda_runtime.h>
#include <math.h>

#define DEPTH 2
#define NQ 4
#define M_CH 512
#define B_SZ 128

// Precomputed Rot gates: [layer][qubit][m][8] = (g00r,g00i,g01r,g01i,g10r,g10i,g11r,g11i)
__device__ float g_gates[DEPTH * NQ * M_CH * 8];

__global__ void gates_kernel(const float* __restrict__ w) {
    int t = blockIdx.x * blockDim.x + threadIdx.x;   // 0 .. 4095
    if (t >= DEPTH * NQ * M_CH) return;
    int m     = t & (M_CH - 1);
    int q     = (t >> 9) & 3;
    int layer = t >> 11;
    // quantum_weights layout: [m][layer][q][3]
    const float* wp = w + m * (DEPTH * NQ * 3) + layer * (NQ * 3) + q * 3;
    float phi = wp[0], theta = wp[1], omega = wp[2];
    float st, ct; sincosf(0.5f * theta,         &st, &ct);
    float sp, cp; sincosf(0.5f * (phi + omega), &sp, &cp);
    float sm, cm; sincosf(0.5f * (phi - omega), &sm, &cm);
    float* g = g_gates + (size_t)t * 8;
    // g00 = e^{-i(phi+omega)/2} c ; g01 = -e^{+i(phi-omega)/2} s
    // g10 = e^{-i(phi-omega)/2} s ; g11 = e^{+i(phi+omega)/2} c
    g[0] =  cp * ct;  g[1] = -sp * ct;
    g[2] = -cm * st;  g[3] = -sm * st;
    g[4] =  cm * st;  g[5] = -sm * st;
    g[6] =  cp * ct;  g[7] =  sp * ct;
}

__global__ __launch_bounds__(512) void qpool_kernel(const float* __restrict__ in,
                                                    float* __restrict__ out) {
    const int b = blockIdx.x;      // 0..127
    const int m = threadIdx.x;     // 0..511
    const float* base = in + (size_t)b * (32 * 32 * M_CH) + m;

    // ---- Pooling: 4 quadrant sums over the 32x32 image for channel m ----
    float a00 = 0.f, a01 = 0.f, a10 = 0.f, a11 = 0.f;
    #pragma unroll 4
    for (int r = 0; r < 16; r++) {
        const float* row = base + (size_t)r * (32 * M_CH);
        #pragma unroll
        for (int c = 0; c < 16; c++)  a00 += __ldg(row + c * M_CH);
        #pragma unroll
        for (int c = 16; c < 32; c++) a01 += __ldg(row + c * M_CH);
    }
    #pragma unroll 4
    for (int r = 16; r < 32; r++) {
        const float* row = base + (size_t)r * (32 * M_CH);
        #pragma unroll
        for (int c = 0; c < 16; c++)  a10 += __ldg(row + c * M_CH);
        #pragma unroll
        for (int c = 16; c < 32; c++) a11 += __ldg(row + c * M_CH);
    }

    const float PI = 3.14159265358979f;
    const float inv = 1.f / 256.f;
    float ang0 = tanhf(a00 * inv) * PI;   // k = i*2 + j : (0,0)
    float ang1 = tanhf(a01 * inv) * PI;   // (0,1)
    float ang2 = tanhf(a10 * inv) * PI;   // (1,0)
    float ang3 = tanhf(a11 * inv) * PI;   // (1,1)

    // ---- RY layer on |0000> : product state, purely real ----
    float s0, c0, s1, c1, s2, c2, s3, c3;
    sincosf(0.5f * ang0, &s0, &c0);
    sincosf(0.5f * ang1, &s1, &c1);
    sincosf(0.5f * ang2, &s2, &c2);
    sincosf(0.5f * ang3, &s3, &c3);

    float re[16], im[16];
    {
        float p0[2] = {c0, s0}, p1[2] = {c1, s1}, p2[2] = {c2, s2}, p3[2] = {c3, s3};
        #pragma unroll
        for (int x = 0; x < 16; x++) {
            re[x] = p0[(x >> 3) & 1] * p1[(x >> 2) & 1] * p2[(x >> 1) & 1] * p3[x & 1];
            im[x] = 0.f;
        }
    }

    // Composition of the 6 CNOTs (0,1)(0,2)(0,3)(1,2)(1,3)(2,3):
    // bits (a,b,c,d) -> (a, a^b, b^c, c^d); new[PERM[x]] = old[x]
    const int PERM[16] = {0, 1, 3, 2, 6, 7, 5, 4, 12, 13, 15, 14, 10, 11, 9, 8};

    #pragma unroll
    for (int layer = 0; layer < DEPTH; layer++) {
        #pragma unroll
        for (int q = 0; q < NQ; q++) {
            const float4* gp =
                (const float4*)(g_gates + ((size_t)((layer * NQ + q) * M_CH + m)) * 8);
            float4 gA = gp[0];   // g00r,g00i,g01r,g01i
            float4 gB = gp[1];   // g10r,g10i,g11r,g11i
            const int mask = 8 >> q;
            #pragma unroll
            for (int i = 0; i < 16; i++) {
                if (i & mask) continue;
                const int j = i | mask;
                float ar = re[i], ai = im[i], br = re[j], bi = im[j];
                re[i] = gA.x * ar - gA.y * ai + gA.z * br - gA.w * bi;
                im[i] = gA.x * ai + gA.y * ar + gA.z * bi + gA.w * br;
                re[j] = gB.x * ar - gB.y * ai + gB.z * br - gB.w * bi;
                im[j] = gB.x * ai + gB.y * ar + gB.z * bi + gB.w * br;
            }
        }
        // CNOT cascade = fixed permutation (register shuffle)
        float tr[16], ti[16];
        #pragma unroll
        for (int x = 0; x < 16; x++) { tr[PERM[x]] = re[x]; ti[PERM[x]] = im[x]; }
        #pragma unroll
        for (int x = 0; x < 16; x++) { re[x] = tr[x]; im[x] = ti[x]; }
    }

    // ---- <Z_0> ----
    float z = 0.f;
    #pragma unroll
    for (int x = 0; x < 8; x++)  z += re[x] * re[x] + im[x] * im[x];
    #pragma unroll
    for (int x = 8; x < 16; x++) z -= re[x] * re[x] + im[x] * im[x];

    out[(size_t)b * M_CH + m] = z;
}

extern "C" void kernel_launch(void* const* d_in, const int* in_sizes, int n_in,
                              void* d_out, int out_size) {
    const float* in = (const float*)d_in[0];
    const float* w  = (const float*)d_in[1];
    // Defensive: inputs is the big tensor (67,108,864 elems), weights tiny (12,288)
    if (n_in >= 2 && in_sizes[0] < in_sizes[1]) {
        const float* t = in; in = w; w = t;
    }
    gates_kernel<<<16, 256>>>(w);
    qpool_kernel<<<B_SZ, 512>>>(in, (float*)d_out);
}